// round 13
// baseline (speedup 1.0000x reference)
#include <cuda_runtime.h>
#include <cuda_bf16.h>

// out[row, k] = clips[row, k - idx] for k >= idx else 0, idx = int(x[row]*N).
// rows = B*C = 1024, N = 32768, fp32. Streaming-bandwidth kernel.
//
// R13: v8 (256-bit) ops, UNROLL=2, NO cache-policy ops. ncu (cold-cache)
// flattered evict_last variants, but the scored warm replay loop regressed:
// pinning the read stream steals L2 from the write stream in steady state.
// Default-policy nc loads + st.cs stores = the cache behavior of the best
// warm-wall rounds (R4/R5), with R12's halved memory-instruction count.

#define BLOCK   256
#define UNROLL  2
#define SEG     (BLOCK * 8 * UNROLL)    // 4096 floats per block

struct f8 { float v[8]; };

__device__ __forceinline__ f8 ld8(const float* p) {
    f8 r;
    asm("ld.global.nc.v8.f32 {%0,%1,%2,%3,%4,%5,%6,%7}, [%8];"
        : "=f"(r.v[0]), "=f"(r.v[1]), "=f"(r.v[2]), "=f"(r.v[3]),
          "=f"(r.v[4]), "=f"(r.v[5]), "=f"(r.v[6]), "=f"(r.v[7])
        : "l"(p));
    return r;
}
__device__ __forceinline__ void st8(float* p, const f8& r) {
    asm volatile("st.global.cs.v8.f32 [%0], {%1,%2,%3,%4,%5,%6,%7,%8};"
                 :: "l"(p),
                    "f"(r.v[0]), "f"(r.v[1]), "f"(r.v[2]), "f"(r.v[3]),
                    "f"(r.v[4]), "f"(r.v[5]), "f"(r.v[6]), "f"(r.v[7])
                 : "memory");
}

__global__ void __launch_bounds__(BLOCK, 8)
RollScheduler_63273458204913_kernel(
    const float* __restrict__ x,
    const float* __restrict__ clips,
    float* __restrict__ out,
    int n)
{
    const int row = blockIdx.y;
    // Match jnp: (x * n).astype(int32) — f32 multiply, truncate toward zero.
    const int idx = (int)(x[row] * (float)n);

    const float* __restrict__ src = clips + (size_t)row * (size_t)n;
    float*       __restrict__ dst = out   + (size_t)row * (size_t)n;

    const int k0 = blockIdx.x * SEG;          // block segment start
    const int kT = k0 + threadIdx.x * 8;      // this thread's first 8-chunk
    const int r8 = (8 - (idx & 7)) & 7;       // (k - idx) & 7 for k%8==0

    // ---- all-zero block ----
    if (k0 + SEG <= idx) {
        f8 z;
        #pragma unroll
        for (int j = 0; j < 8; j++) z.v[j] = 0.0f;
        #pragma unroll
        for (int u = 0; u < UNROLL; u++)
            st8(dst + kT + u * (BLOCK * 8), z);
        return;
    }

    // ---- fully-valid fast path? (block-uniform) ----
    const bool fast = (k0 - idx - r8 >= 0) &&
                      (r8 == 0 || (k0 + SEG + 8 - idx - r8) <= n);

    if (fast) {
        if (r8 == 0) {
            const float* s = src + (kT - idx);
            #pragma unroll
            for (int u = 0; u < UNROLL; u++)
                st8(dst + kT + u * (BLOCK * 8), ld8(s + u * (BLOCK * 8)));
        } else {
            const float* a = src + (kT - idx - r8);   // 32B-aligned
            #define ROTCASE(R)                                              \
                do {                                                        \
                    _Pragma("unroll")                                       \
                    for (int u = 0; u < UNROLL; u++) {                      \
                        const f8 lo = ld8(a + u * (BLOCK * 8));             \
                        const f8 hi = ld8(a + u * (BLOCK * 8) + 8);         \
                        f8 o;                                               \
                        _Pragma("unroll")                                   \
                        for (int j = 0; j < 8; j++)                         \
                            o.v[j] = ((R) + j < 8) ? lo.v[(R) + j]          \
                                                   : hi.v[(R) + j - 8];     \
                        st8(dst + kT + u * (BLOCK * 8), o);                 \
                    }                                                       \
                } while (0)
            switch (r8) {   // block-uniform
                case 1: ROTCASE(1); break;
                case 2: ROTCASE(2); break;
                case 3: ROTCASE(3); break;
                case 4: ROTCASE(4); break;
                case 5: ROTCASE(5); break;
                case 6: ROTCASE(6); break;
                default: ROTCASE(7); break;
            }
            #undef ROTCASE
        }
        return;
    }

    // ---- boundary / edge block: guarded scalar (rare, ~1 block per row) ----
    #pragma unroll
    for (int u = 0; u < UNROLL; u++) {
        const int k = kT + u * (BLOCK * 8);
        if (k >= n) break;
        const int base = k - idx;
        f8 o;
        #pragma unroll
        for (int j = 0; j < 8; j++) {
            const int b = base + j;   // b <= n-1 always (idx >= 0, k+7 < n)
            o.v[j] = (b >= 0) ? __ldg(src + b) : 0.0f;
        }
        st8(dst + k, o);
    }
}

extern "C" void kernel_launch(void* const* d_in, const int* in_sizes, int n_in,
                              void* d_out, int out_size) {
    const float* x     = (const float*)d_in[0];   // (B, C)
    const float* clips = (const float*)d_in[1];   // (B, C, N)
    // d_in[2] = actual — unused in the forward computation.
    float* out = (float*)d_out;

    const int rows = in_sizes[0];                 // B*C = 1024
    const int n    = in_sizes[1] / in_sizes[0];   // N = 32768

    dim3 block(BLOCK);
    dim3 grid((n + SEG - 1) / SEG, rows);         // 8 x 1024 = 8192 blocks
    RollScheduler_63273458204913_kernel<<<grid, block>>>(x, clips, out, n);
}

// round 14
// speedup vs baseline: 1.0459x; 1.0459x over previous
#include <cuda_runtime.h>
#include <cuda_bf16.h>

// out[row, k] = clips[row, k - idx] for k >= idx else 0, idx = int(x[row]*N).
// rows = B*C = 1024, N = 32768, fp32. Streaming-bandwidth kernel.
//
// R14: the scored (warm-replay) metric favors the v4 __ldcs/__stcs family
// (R4/R5/R8 walls 34.9-35.3) over v8-asm (36.6-37.2), even though cold ncu
// says the opposite. So: v4 intrinsics, UNROLL=4 (R4's per-thread work),
// loads/stores interleaved in PAIRS to keep live regs ~32, and
// launch_bounds(256,8) for full 64-warp/SM occupancy (R5's lever).

#define BLOCK   256
#define UNROLL  4
#define PAIRS   (UNROLL / 2)
#define SEG     (BLOCK * 4 * UNROLL)   // 4096 floats per block

__device__ __forceinline__ float4 ldcs4(const float* p) {
    return __ldcs(reinterpret_cast<const float4*>(p));
}
__device__ __forceinline__ void stcs4(float* p, float4 v) {
    __stcs(reinterpret_cast<float4*>(p), v);
}

__global__ void __launch_bounds__(BLOCK, 8)
RollScheduler_63273458204913_kernel(
    const float* __restrict__ x,
    const float* __restrict__ clips,
    float* __restrict__ out,
    int n)
{
    const int row = blockIdx.y;
    // Match jnp: (x * n).astype(int32) — f32 multiply, truncate toward zero.
    const int idx = (int)(x[row] * (float)n);

    const float* __restrict__ src = clips + (size_t)row * (size_t)n;
    float*       __restrict__ dst = out   + (size_t)row * (size_t)n;

    const int k0 = blockIdx.x * SEG;          // block segment start
    const int kT = k0 + threadIdx.x * 4;      // this thread's first chunk
    const int r  = (4 - (idx & 3)) & 3;       // (k - idx) & 3 for k%4==0

    // ---- all-zero block ----
    if (k0 + SEG <= idx) {
        const float4 z = make_float4(0.f, 0.f, 0.f, 0.f);
        #pragma unroll
        for (int u = 0; u < UNROLL; u++)
            stcs4(dst + kT + u * (BLOCK * 4), z);
        return;
    }

    // ---- fully-valid fast path? (block-uniform) ----
    const bool fast = (k0 - idx - r >= 0) &&
                      (r == 0 || (k0 + SEG + 4 - idx - r) <= n);

    if (fast) {
        if (r == 0) {
            const float* s = src + (kT - idx);
            #pragma unroll
            for (int p = 0; p < PAIRS; p++) {
                const int u0 = 2 * p, u1 = 2 * p + 1;
                float4 v0 = ldcs4(s + u0 * (BLOCK * 4));
                float4 v1 = ldcs4(s + u1 * (BLOCK * 4));
                stcs4(dst + kT + u0 * (BLOCK * 4), v0);
                stcs4(dst + kT + u1 * (BLOCK * 4), v1);
            }
        } else {
            const float* s = src + (kT - idx - r);   // 16B-aligned
            #pragma unroll
            for (int p = 0; p < PAIRS; p++) {
                const int u0 = 2 * p, u1 = 2 * p + 1;
                float4 lo0 = ldcs4(s + u0 * (BLOCK * 4));
                float4 hi0 = ldcs4(s + u0 * (BLOCK * 4) + 4);
                float4 lo1 = ldcs4(s + u1 * (BLOCK * 4));
                float4 hi1 = ldcs4(s + u1 * (BLOCK * 4) + 4);
                float4 v0, v1;
                if (r == 1) {
                    v0 = make_float4(lo0.y, lo0.z, lo0.w, hi0.x);
                    v1 = make_float4(lo1.y, lo1.z, lo1.w, hi1.x);
                } else if (r == 2) {
                    v0 = make_float4(lo0.z, lo0.w, hi0.x, hi0.y);
                    v1 = make_float4(lo1.z, lo1.w, hi1.x, hi1.y);
                } else {
                    v0 = make_float4(lo0.w, hi0.x, hi0.y, hi0.z);
                    v1 = make_float4(lo1.w, hi1.x, hi1.y, hi1.z);
                }
                stcs4(dst + kT + u0 * (BLOCK * 4), v0);
                stcs4(dst + kT + u1 * (BLOCK * 4), v1);
            }
        }
        return;
    }

    // ---- boundary / edge block: guarded scalar (rare, ~1 block per row) ----
    #pragma unroll
    for (int u = 0; u < UNROLL; u++) {
        const int k = kT + u * (BLOCK * 4);
        if (k >= n) break;
        const int base = k - idx;   // base+3 <= n-1 always (idx >= 0)
        float4 v;
        v.x = (base     >= 0) ? src[base]     : 0.0f;
        v.y = (base + 1 >= 0) ? src[base + 1] : 0.0f;
        v.z = (base + 2 >= 0) ? src[base + 2] : 0.0f;
        v.w = (base + 3 >= 0) ? src[base + 3] : 0.0f;
        stcs4(dst + k, v);
    }
}

extern "C" void kernel_launch(void* const* d_in, const int* in_sizes, int n_in,
                              void* d_out, int out_size) {
    const float* x     = (const float*)d_in[0];   // (B, C)
    const float* clips = (const float*)d_in[1];   // (B, C, N)
    // d_in[2] = actual — unused in the forward computation.
    float* out = (float*)d_out;

    const int rows = in_sizes[0];                 // B*C = 1024
    const int n    = in_sizes[1] / in_sizes[0];   // N = 32768

    dim3 block(BLOCK);
    dim3 grid((n + SEG - 1) / SEG, rows);         // 8 x 1024 = 8192 blocks
    RollScheduler_63273458204913_kernel<<<grid, block>>>(x, clips, out, n);
}

// round 15
// speedup vs baseline: 1.0622x; 1.0155x over previous
#include <cuda_runtime.h>
#include <cuda_bf16.h>

// out[row, k] = clips[row, k - idx] for k >= idx else 0, idx = int(x[row]*N).
// rows = B*C = 1024, N = 32768, fp32. Streaming-bandwidth kernel.
//
// R15 = R4 verbatim (best measured wall: 34.9us). Session conclusion: kernel
// is at the write-dominated HBM floor (~145 MB/replay @ ~5 TB/s); remaining
// wall variance across variants is harness noise. Re-bench to confirm and
// lock in. UNROLL=4 batched v4 loads, __ldcs/__stcs, 4 CTAs/SM, 8192 blocks.

#define BLOCK   256
#define UNROLL  4
#define SEG     (BLOCK * 4 * UNROLL)   // 4096 floats per block

__device__ __forceinline__ float4 ldcs4(const float* p) {
    return __ldcs(reinterpret_cast<const float4*>(p));
}
__device__ __forceinline__ void stcs4(float* p, float4 v) {
    __stcs(reinterpret_cast<float4*>(p), v);
}

__global__ void __launch_bounds__(BLOCK, 4)
RollScheduler_63273458204913_kernel(
    const float* __restrict__ x,
    const float* __restrict__ clips,
    float* __restrict__ out,
    int n)
{
    const int row = blockIdx.y;
    // Match jnp: (x * n).astype(int32) — f32 multiply, truncate toward zero.
    const int idx = (int)(x[row] * (float)n);

    const float* __restrict__ src = clips + (size_t)row * (size_t)n;
    float*       __restrict__ dst = out   + (size_t)row * (size_t)n;

    const int k0 = blockIdx.x * SEG;          // block segment start
    const int kT = k0 + threadIdx.x * 4;      // this thread's first chunk
    const int r  = (4 - (idx & 3)) & 3;       // (k - idx) & 3 for k%4==0

    // ---- all-zero block ----
    if (k0 + SEG <= idx) {
        const float4 z = make_float4(0.f, 0.f, 0.f, 0.f);
        #pragma unroll
        for (int u = 0; u < UNROLL; u++)
            stcs4(dst + kT + u * (BLOCK * 4), z);
        return;
    }

    // ---- fully-valid fast path? (block-uniform) ----
    const bool fast = (k0 - idx - r >= 0) &&
                      (r == 0 || (k0 + SEG + 4 - idx - r) <= n);

    if (fast) {
        if (r == 0) {
            const float* s = src + (kT - idx);
            float4 v[UNROLL];
            #pragma unroll
            for (int u = 0; u < UNROLL; u++)
                v[u] = ldcs4(s + u * (BLOCK * 4));
            #pragma unroll
            for (int u = 0; u < UNROLL; u++)
                stcs4(dst + kT + u * (BLOCK * 4), v[u]);
        } else {
            const float* s = src + (kT - idx - r);   // 16B-aligned
            float4 lo[UNROLL], hi[UNROLL];
            #pragma unroll
            for (int u = 0; u < UNROLL; u++) {
                lo[u] = ldcs4(s + u * (BLOCK * 4));
                hi[u] = ldcs4(s + u * (BLOCK * 4) + 4);
            }
            #pragma unroll
            for (int u = 0; u < UNROLL; u++) {
                float4 v;
                if (r == 1)      v = make_float4(lo[u].y, lo[u].z, lo[u].w, hi[u].x);
                else if (r == 2) v = make_float4(lo[u].z, lo[u].w, hi[u].x, hi[u].y);
                else             v = make_float4(lo[u].w, hi[u].x, hi[u].y, hi[u].z);
                stcs4(dst + kT + u * (BLOCK * 4), v);
            }
        }
        return;
    }

    // ---- boundary / edge block: guarded scalar (rare, ~1 block per row) ----
    #pragma unroll
    for (int u = 0; u < UNROLL; u++) {
        const int k = kT + u * (BLOCK * 4);
        if (k >= n) break;
        const int base = k - idx;   // base+3 <= n-1 always (idx >= 0)
        float4 v;
        v.x = (base     >= 0) ? src[base]     : 0.0f;
        v.y = (base + 1 >= 0) ? src[base + 1] : 0.0f;
        v.z = (base + 2 >= 0) ? src[base + 2] : 0.0f;
        v.w = (base + 3 >= 0) ? src[base + 3] : 0.0f;
        stcs4(dst + k, v);
    }
}

extern "C" void kernel_launch(void* const* d_in, const int* in_sizes, int n_in,
                              void* d_out, int out_size) {
    const float* x     = (const float*)d_in[0];   // (B, C)
    const float* clips = (const float*)d_in[1];   // (B, C, N)
    // d_in[2] = actual — unused in the forward computation.
    float* out = (float*)d_out;

    const int rows = in_sizes[0];                 // B*C = 1024
    const int n    = in_sizes[1] / in_sizes[0];   // N = 32768

    dim3 block(BLOCK);
    dim3 grid((n + SEG - 1) / SEG, rows);         // 8 x 1024 = 8192 blocks
    RollScheduler_63273458204913_kernel<<<grid, block>>>(x, clips, out, n);
}

// round 16
// speedup vs baseline: 1.0651x; 1.0027x over previous
#include <cuda_runtime.h>
#include <cuda_bf16.h>

// out[row, k] = clips[row, k - idx] for k >= idx else 0, idx = int(x[row]*N).
// rows = B*C = 1024, N = 32768, fp32. Streaming-bandwidth kernel.
//
// R16 = R4 (twice-confirmed best: 34.9/35.0us wall) with min-blocks raised
// 4 -> 5: at regs=44, 5 CTAs/SM fit the register file (56320 <= 64K), so
// launch_bounds(256,4) was leaving ~11% occupancy on the table with zero
// change to the memory-op stream. Everything else identical to R4.

#define BLOCK   256
#define UNROLL  4
#define SEG     (BLOCK * 4 * UNROLL)   // 4096 floats per block

__device__ __forceinline__ float4 ldcs4(const float* p) {
    return __ldcs(reinterpret_cast<const float4*>(p));
}
__device__ __forceinline__ void stcs4(float* p, float4 v) {
    __stcs(reinterpret_cast<float4*>(p), v);
}

__global__ void __launch_bounds__(BLOCK, 5)
RollScheduler_63273458204913_kernel(
    const float* __restrict__ x,
    const float* __restrict__ clips,
    float* __restrict__ out,
    int n)
{
    const int row = blockIdx.y;
    // Match jnp: (x * n).astype(int32) — f32 multiply, truncate toward zero.
    const int idx = (int)(x[row] * (float)n);

    const float* __restrict__ src = clips + (size_t)row * (size_t)n;
    float*       __restrict__ dst = out   + (size_t)row * (size_t)n;

    const int k0 = blockIdx.x * SEG;          // block segment start
    const int kT = k0 + threadIdx.x * 4;      // this thread's first chunk
    const int r  = (4 - (idx & 3)) & 3;       // (k - idx) & 3 for k%4==0

    // ---- all-zero block ----
    if (k0 + SEG <= idx) {
        const float4 z = make_float4(0.f, 0.f, 0.f, 0.f);
        #pragma unroll
        for (int u = 0; u < UNROLL; u++)
            stcs4(dst + kT + u * (BLOCK * 4), z);
        return;
    }

    // ---- fully-valid fast path? (block-uniform) ----
    const bool fast = (k0 - idx - r >= 0) &&
                      (r == 0 || (k0 + SEG + 4 - idx - r) <= n);

    if (fast) {
        if (r == 0) {
            const float* s = src + (kT - idx);
            float4 v[UNROLL];
            #pragma unroll
            for (int u = 0; u < UNROLL; u++)
                v[u] = ldcs4(s + u * (BLOCK * 4));
            #pragma unroll
            for (int u = 0; u < UNROLL; u++)
                stcs4(dst + kT + u * (BLOCK * 4), v[u]);
        } else {
            const float* s = src + (kT - idx - r);   // 16B-aligned
            float4 lo[UNROLL], hi[UNROLL];
            #pragma unroll
            for (int u = 0; u < UNROLL; u++) {
                lo[u] = ldcs4(s + u * (BLOCK * 4));
                hi[u] = ldcs4(s + u * (BLOCK * 4) + 4);
            }
            #pragma unroll
            for (int u = 0; u < UNROLL; u++) {
                float4 v;
                if (r == 1)      v = make_float4(lo[u].y, lo[u].z, lo[u].w, hi[u].x);
                else if (r == 2) v = make_float4(lo[u].z, lo[u].w, hi[u].x, hi[u].y);
                else             v = make_float4(lo[u].w, hi[u].x, hi[u].y, hi[u].z);
                stcs4(dst + kT + u * (BLOCK * 4), v);
            }
        }
        return;
    }

    // ---- boundary / edge block: guarded scalar (rare, ~1 block per row) ----
    #pragma unroll
    for (int u = 0; u < UNROLL; u++) {
        const int k = kT + u * (BLOCK * 4);
        if (k >= n) break;
        const int base = k - idx;   // base+3 <= n-1 always (idx >= 0)
        float4 v;
        v.x = (base     >= 0) ? src[base]     : 0.0f;
        v.y = (base + 1 >= 0) ? src[base + 1] : 0.0f;
        v.z = (base + 2 >= 0) ? src[base + 2] : 0.0f;
        v.w = (base + 3 >= 0) ? src[base + 3] : 0.0f;
        stcs4(dst + k, v);
    }
}

extern "C" void kernel_launch(void* const* d_in, const int* in_sizes, int n_in,
                              void* d_out, int out_size) {
    const float* x     = (const float*)d_in[0];   // (B, C)
    const float* clips = (const float*)d_in[1];   // (B, C, N)
    // d_in[2] = actual — unused in the forward computation.
    float* out = (float*)d_out;

    const int rows = in_sizes[0];                 // B*C = 1024
    const int n    = in_sizes[1] / in_sizes[0];   // N = 32768

    dim3 block(BLOCK);
    dim3 grid((n + SEG - 1) / SEG, rows);         // 8 x 1024 = 8192 blocks
    RollScheduler_63273458204913_kernel<<<grid, block>>>(x, clips, out, n);
}